// round 14
// baseline (speedup 1.0000x reference)
#include <cuda_runtime.h>
#include <stdint.h>

#define NN 20000
#define NE 320000
#define LDIM 128
#define TILE 128              // rows per CTA (edge kernel)
#define TILEN 64              // rows per CTA (node-side kernels)
#define ASTR 132              // padded A/U row stride (floats)
#define NT 256                // threads (edge)
#define NTN 128               // threads (node-side)
#define KQ 32                 // k-quarter staged per cp.async group
#define CHI 64                // column offset of second 4-col chunk per lane
#define NLAYERS 5

#define WQ_FLOATS (KQ * LDIM)                       // 4096 floats = 16KB
#define SMEM_EDGEK ((2 * WQ_FLOATS + TILE * ASTR) * 4 + 2 * TILE * 4)
#define SMEM_NODE  ((2 * WQ_FLOATS + TILEN * ASTR) * 4)

// -------- scratch (static device allocations; no runtime alloc) --------
__device__ float g_h[NN * LDIM];
__device__ float g_P[NN * LDIM];
__device__ float g_Q[NN * LDIM];
__device__ float g_agg[NN * LDIM];
__device__ float g_e[NE * LDIM];

typedef unsigned long long u64t;

// -------- packed fp32x2 primitives --------
__device__ __forceinline__ void ffma2(u64t& d, u64t a, u64t b) {
    asm("fma.rn.f32x2 %0, %1, %2, %0;" : "+l"(d) : "l"(a), "l"(b));
}
__device__ __forceinline__ u64t pack2(float x, float y) {
    u64t v; asm("mov.b64 %0, {%1, %2};" : "=l"(v) : "f"(x), "f"(y)); return v;
}
__device__ __forceinline__ float2 unpack2(u64t v) {
    float2 f; asm("mov.b64 {%0, %1}, %2;" : "=f"(f.x), "=f"(f.y) : "l"(v)); return f;
}
__device__ __forceinline__ float prelu1(float v, float a) { return v > 0.f ? v : a * v; }

__device__ __forceinline__ void red_add_v4(float* addr, float4 v) {
    asm volatile("red.global.add.v4.f32 [%0], {%1,%2,%3,%4};"
                 :: "l"(addr), "f"(v.x), "f"(v.y), "f"(v.z), "f"(v.w)
                 : "memory");
}

// -------- cp.async staging --------
__device__ __forceinline__ uint32_t smem_u32(const void* p) {
    uint32_t a;
    asm("{ .reg .u64 t; cvta.to.shared.u64 t, %1; cvt.u32.u64 %0, t; }" : "=r"(a) : "l"(p));
    return a;
}
__device__ __forceinline__ void cpa16(uint32_t d, const float* __restrict__ s) {
    asm volatile("cp.async.cg.shared.global [%0], [%1], 16;" :: "r"(d), "l"(s));
}
template<int NTT>
__device__ __forceinline__ void stage_w(float* buf, const float* __restrict__ w, int tid) {
    uint32_t d = smem_u32(buf + tid * 4);
    const float* s = w + tid * 4;
#pragma unroll
    for (int i = 0; i < WQ_FLOATS / (NTT * 4); ++i)
        cpa16(d + i * NTT * 16, s + i * NTT * 4);
    asm volatile("cp.async.commit_group;" ::: "memory");
}
#define CPA_WAIT_ALL() asm volatile("cp.async.wait_group 0;" ::: "memory")

// -------- smem fills --------
template<int NTT, int TILER>
__device__ __forceinline__ void fill_rows(float* As, const float* __restrict__ src,
                                          int r0, int nrows, int tid) {
    for (int i = tid * 4; i < TILER * LDIM; i += NTT * 4) {
        int r = i >> 7;
        int k = i & (LDIM - 1);
        int gr = r0 + r; if (gr >= nrows) gr = nrows - 1;
        *(float4*)(As + r * ASTR + k) = *(const float4*)(src + (size_t)gr * LDIM + k);
    }
}

// -------- core packed GEMM (column-paired accumulators, 16 rows/warp) --------
// Body of one k4 step
#define GEMM_K4_BODY(As, Ws, AS, k, row_base, c0, acc)                                  \
    {                                                                                   \
        float4 av[8];                                                                   \
        _Pragma("unroll")                                                               \
        for (int r = 0; r < 8; ++r)                                                     \
            av[r] = *(const float4*)((As) + (row_base + r) * (AS) + (k));               \
        _Pragma("unroll")                                                               \
        for (int kk = 0; kk < 4; ++kk) {                                                \
            const float* wr = (Ws) + ((k) + kk) * LDIM + c0;                            \
            ulonglong2 w0 = *(const ulonglong2*)(wr);                                   \
            ulonglong2 w1 = *(const ulonglong2*)(wr + CHI);                             \
            _Pragma("unroll")                                                           \
            for (int r = 0; r < 8; ++r) {                                               \
                float a = (kk == 0) ? av[r].x : (kk == 1) ? av[r].y                     \
                        : (kk == 2) ? av[r].z : av[r].w;                                \
                u64t ad = pack2(a, a);                                                  \
                ffma2(acc[r][0], ad, w0.x);                                             \
                ffma2(acc[r][1], ad, w0.y);                                             \
                ffma2(acc[r][2], ad, w1.x);                                             \
                ffma2(acc[r][3], ad, w1.y);                                             \
            }                                                                           \
        }                                                                               \
    }

// edge version: moderate unroll (reg cap 128)
template<int K, int AS>
__device__ __forceinline__ void gemm_cp(const float* __restrict__ As,
                                        const float* __restrict__ Ws,
                                        int row_base, int c0, u64t acc[8][4]) {
#pragma unroll 2
    for (int k = 0; k < K; k += 4)
        GEMM_K4_BODY(As, Ws, AS, k, row_base, c0, acc)
}

// node version: full unroll (reg cap 170 at launch_bounds(128,3))
template<int K, int AS>
__device__ __forceinline__ void gemm_cpf(const float* __restrict__ As,
                                         const float* __restrict__ Ws,
                                         int row_base, int c0, u64t acc[8][4]) {
#pragma unroll
    for (int k = 0; k < K; k += 4)
        GEMM_K4_BODY(As, Ws, AS, k, row_base, c0, acc)
}

__device__ __forceinline__ void acc_initb(u64t acc[8][4], const float* __restrict__ b, int c0) {
    ulonglong2 b0 = *(const ulonglong2*)(b + c0);
    ulonglong2 b1 = *(const ulonglong2*)(b + c0 + CHI);
#pragma unroll
    for (int r = 0; r < 8; ++r) {
        acc[r][0] = b0.x; acc[r][1] = b0.y; acc[r][2] = b1.x; acc[r][3] = b1.y;
    }
}
__device__ __forceinline__ void acc_init0(u64t acc[8][4]) {
#pragma unroll
    for (int r = 0; r < 8; ++r)
        acc[r][0] = acc[r][1] = acc[r][2] = acc[r][3] = 0ull;
}
__device__ __forceinline__ void acc_fin2(const u64t a[4], float4& lo, float4& hi) {
    float2 f0 = unpack2(a[0]), f1 = unpack2(a[1]), f2 = unpack2(a[2]), f3 = unpack2(a[3]);
    lo = make_float4(f0.x, f0.y, f1.x, f1.y);
    hi = make_float4(f2.x, f2.y, f3.x, f3.y);
}
__device__ __forceinline__ void store_U(float* U, u64t acc[8][4],
                                        int row_base, int c0, float al) {
#pragma unroll
    for (int r = 0; r < 8; ++r) {
        float4 lo, hi; acc_fin2(acc[r], lo, hi);
        lo.x = prelu1(lo.x, al); lo.y = prelu1(lo.y, al);
        lo.z = prelu1(lo.z, al); lo.w = prelu1(lo.w, al);
        hi.x = prelu1(hi.x, al); hi.y = prelu1(hi.y, al);
        hi.z = prelu1(hi.z, al); hi.w = prelu1(hi.w, al);
        float* p = U + (row_base + r) * ASTR + c0;
        *(float4*)(p)       = lo;
        *(float4*)(p + CHI) = hi;
    }
}
__device__ __forceinline__ void tmap(int tid, int& row_base, int& c0) {
    int wy = tid >> 5;
    int lane = tid & 31;
    row_base = wy * 16 + (lane >> 4) * 8;
    c0 = (lane & 15) * 4;
}

// Run 4 streamed quarters of one 128-K GEMM (edge / node variants).
#define GEMM_STREAM4(NTT, WbA, WbB, As, wsrc, nxt, row_base, c0, acc)                    \
    do {                                                                                 \
        _Pragma("unroll")                                                                \
        for (int q = 0; q < 4; ++q) {                                                    \
            CPA_WAIT_ALL(); __syncthreads();                                             \
            const float* _n = (q < 3) ? ((wsrc) + (q + 1) * WQ_FLOATS) : (nxt);          \
            if (_n) stage_w<NTT>((q & 1) ? (WbA) : (WbB), _n, tid);                      \
            gemm_cp<KQ, ASTR>((As) + q * KQ, (q & 1) ? (WbB) : (WbA), row_base, c0, acc);\
        }                                                                                \
    } while (0)

#define GEMM_STREAM4F(NTT, WbA, WbB, As, wsrc, nxt, row_base, c0, acc)                    \
    do {                                                                                  \
        _Pragma("unroll")                                                                 \
        for (int q = 0; q < 4; ++q) {                                                     \
            CPA_WAIT_ALL(); __syncthreads();                                              \
            const float* _n = (q < 3) ? ((wsrc) + (q + 1) * WQ_FLOATS) : (nxt);           \
            if (_n) stage_w<NTT>((q & 1) ? (WbA) : (WbB), _n, tid);                       \
            gemm_cpf<KQ, ASTR>((As) + q * KQ, (q & 1) ? (WbB) : (WbA), row_base, c0, acc);\
        }                                                                                 \
    } while (0)

// write P/agg-zero epilogue
__device__ __forceinline__ void store_P_agg(u64t acc[8][4], int r0, int row_base, int c0) {
    float4 z = make_float4(0.f, 0.f, 0.f, 0.f);
#pragma unroll
    for (int r = 0; r < 8; ++r) {
        int gr = r0 + row_base + r;
        if (gr < NN) {
            float4 lo, hi; acc_fin2(acc[r], lo, hi);
            *(float4*)(g_P + (size_t)gr * LDIM + c0)         = lo;
            *(float4*)(g_P + (size_t)gr * LDIM + c0 + CHI)   = hi;
            *(float4*)(g_agg + (size_t)gr * LDIM + c0)       = z;
            *(float4*)(g_agg + (size_t)gr * LDIM + c0 + CHI) = z;
        }
    }
}
__device__ __forceinline__ void store_Qv(u64t acc[8][4], int r0, int row_base, int c0) {
#pragma unroll
    for (int r = 0; r < 8; ++r) {
        int gr = r0 + row_base + r;
        if (gr < NN) {
            float4 lo, hi; acc_fin2(acc[r], lo, hi);
            *(float4*)(g_Q + (size_t)gr * LDIM + c0)       = lo;
            *(float4*)(g_Q + (size_t)gr * LDIM + c0 + CHI) = hi;
        }
    }
}

// ============================ encoder (node fused with layer-0 P/Q; edge plain) ====
template<int K1, int K1P>
__global__ __launch_bounds__(NTN, 3)
void encoder_kernel(const float* __restrict__ in,
                    const float* __restrict__ w1, const float* __restrict__ b1,
                    const float* __restrict__ aslope,
                    const float* __restrict__ w2, const float* __restrict__ b2,
                    float* __restrict__ out, int nrows,
                    const float* __restrict__ wl /* le_w1 layer0 base or null */) {
    extern __shared__ float sm[];
    float* Wb0 = sm;
    float* Wb1 = sm + WQ_FLOATS;
    float* As = sm + 2 * WQ_FLOATS;
    int tid = threadIdx.x;
    int row_base, c0; tmap(tid, row_base, c0);
    int r0 = blockIdx.x * TILEN;

    for (int i = tid; i < TILEN * K1P; i += NTN) {
        int r = i / K1P, k = i - r * K1P;
        int gr = r0 + r; if (gr >= nrows) gr = nrows - 1;
        As[i] = (k < K1) ? in[(size_t)gr * K1 + k] : 0.f;
    }
    for (int i = tid; i < K1P * LDIM; i += NTN)
        Wb0[i] = (i < K1 * LDIM) ? w1[i] : 0.f;
    __syncthreads();

    stage_w<NTN>(Wb1, w2, tid);            // prefetch W2 q0 during GEMM1 (q0 -> Wb1)
    float al = *aslope;

    u64t acc[8][4];
    acc_initb(acc, b1, c0);
    gemm_cpf<K1P, K1P>(As, Wb0, row_base, c0, acc);

    __syncthreads();
    store_U(As, acc, row_base, c0, al);
    acc_initb(acc, b2, c0);

    GEMM_STREAM4F(NTN, Wb1, Wb0, As, w2, wl, row_base, c0, acc);  // h; prefetch W1a q0

    __syncthreads();
#pragma unroll
    for (int r = 0; r < 8; ++r) {
        int gr = r0 + row_base + r;
        float4 lo, hi; acc_fin2(acc[r], lo, hi);
        if (gr < nrows) {
            *(float4*)(out + (size_t)gr * LDIM + c0)       = lo;
            *(float4*)(out + (size_t)gr * LDIM + c0 + CHI) = hi;
        }
        if (wl) {
            float* p = As + (row_base + r) * ASTR + c0;
            *(float4*)(p)       = lo;
            *(float4*)(p + CHI) = hi;
        }
    }
    if (!wl) return;
    __syncthreads();

    const float* w1b = wl + 4 * WQ_FLOATS;
    acc_init0(acc);
    GEMM_STREAM4F(NTN, Wb1, Wb0, As, wl, w1b, row_base, c0, acc);   // P
    store_P_agg(acc, r0, row_base, c0);
    acc_init0(acc);
    GEMM_STREAM4F(NTN, Wb1, Wb0, As, w1b, (const float*)0, row_base, c0, acc);  // Q
    store_Qv(acc, r0, row_base, c0);
}

// ============================ per-layer: edge messages + scatter ============================
__global__ __launch_bounds__(NT, 2)
void edge_kernel(const int* __restrict__ eidx,
                 const float* __restrict__ wl,
                 const float* __restrict__ b1, const float* __restrict__ aslope,
                 const float* __restrict__ w2, const float* __restrict__ b2) {
    extern __shared__ float sm[];
    float* Wb0 = sm;
    float* Wb1 = sm + WQ_FLOATS;
    float* As = sm + 2 * WQ_FLOATS;
    int* sdst = (int*)(As + TILE * ASTR);
    int* ssrc = sdst + TILE;
    int tid = threadIdx.x;
    int row_base, c0; tmap(tid, row_base, c0);
    size_t e0 = (size_t)blockIdx.x * TILE;

    const float* w1c = wl + 256 * LDIM;
    stage_w<NT>(Wb0, w1c, tid);                      // W1c q0
    fill_rows<NT, TILE>(As, g_e + e0 * LDIM, 0, TILE, tid);
    if (tid < TILE) {
        ssrc[tid] = eidx[e0 + tid];
        sdst[tid] = eidx[NE + e0 + tid];
    }
    __syncthreads();

    float al = *aslope;
    float4 ba = *(const float4*)(b1 + c0);
    float4 bb = *(const float4*)(b1 + c0 + CHI);
    u64t acc[8][4];
#pragma unroll
    for (int r = 0; r < 8; ++r) {
        int d = sdst[row_base + r];
        int s = ssrc[row_base + r];
        float4 Pa = *(const float4*)(g_P + (size_t)d * LDIM + c0);
        float4 Pb = *(const float4*)(g_P + (size_t)d * LDIM + c0 + CHI);
        float4 Qa = *(const float4*)(g_Q + (size_t)s * LDIM + c0);
        float4 Qb = *(const float4*)(g_Q + (size_t)s * LDIM + c0 + CHI);
        acc[r][0] = pack2(ba.x + Pa.x + Qa.x, ba.y + Pa.y + Qa.y);
        acc[r][1] = pack2(ba.z + Pa.z + Qa.z, ba.w + Pa.w + Qa.w);
        acc[r][2] = pack2(bb.x + Pb.x + Qb.x, bb.y + Pb.y + Qb.y);
        acc[r][3] = pack2(bb.z + Pb.z + Qb.z, bb.w + Pb.w + Qb.w);
    }
    GEMM_STREAM4(NT, Wb0, Wb1, As, w1c, w2, row_base, c0, acc);   // W1c, prefetch W2 q0

    __syncthreads();
    store_U(As, acc, row_base, c0, al);
    acc_initb(acc, b2, c0);
    GEMM_STREAM4(NT, Wb0, Wb1, As, w2, (const float*)0, row_base, c0, acc);  // W2

#pragma unroll
    for (int r = 0; r < 8; ++r) {
        int d = sdst[row_base + r];
        float4 lo, hi; acc_fin2(acc[r], lo, hi);
        red_add_v4(g_agg + (size_t)d * LDIM + c0, lo);
        red_add_v4(g_agg + (size_t)d * LDIM + c0 + CHI, hi);
    }
}

// ============================ per-layer: node update (fused with next-layer P/Q) ====
__global__ __launch_bounds__(NTN, 3)
void node_kernel(const float* __restrict__ wn1,
                 const float* __restrict__ b1, const float* __restrict__ aslope,
                 const float* __restrict__ w2, const float* __restrict__ b2,
                 const float* __restrict__ wl_next /* le_w1 next layer or null */) {
    extern __shared__ float sm[];
    float* Wb0 = sm;
    float* Wb1 = sm + WQ_FLOATS;
    float* As = sm + 2 * WQ_FLOATS;
    int tid = threadIdx.x;
    int row_base, c0; tmap(tid, row_base, c0);
    int r0 = blockIdx.x * TILEN;

    const float* wagg = wn1 + 4 * WQ_FLOATS;
    stage_w<NTN>(Wb0, wn1, tid);
    fill_rows<NTN, TILEN>(As, g_h, r0, NN, tid);
    __syncthreads();

    float al = *aslope;
    u64t acc[8][4];
    acc_initb(acc, b1, c0);
    GEMM_STREAM4F(NTN, Wb0, Wb1, As, wn1, wagg, row_base, c0, acc);   // h side

    __syncthreads();
    fill_rows<NTN, TILEN>(As, g_agg, r0, NN, tid);
    GEMM_STREAM4F(NTN, Wb0, Wb1, As, wagg, w2, row_base, c0, acc);    // agg side

    __syncthreads();
    store_U(As, acc, row_base, c0, al);
    acc_initb(acc, b2, c0);
    GEMM_STREAM4F(NTN, Wb0, Wb1, As, w2, wl_next, row_base, c0, acc); // W2; prefetch W1a

    __syncthreads();
#pragma unroll
    for (int r = 0; r < 8; ++r) {
        int gr = r0 + row_base + r;
        if (gr < NN) {
            float4 lo, hi; acc_fin2(acc[r], lo, hi);
            float* hp = g_h + (size_t)gr * LDIM + c0;
            float4 h0 = *(float4*)(hp);
            float4 h1 = *(float4*)(hp + CHI);
            h0.x += lo.x; h0.y += lo.y; h0.z += lo.z; h0.w += lo.w;
            h1.x += hi.x; h1.y += hi.y; h1.z += hi.z; h1.w += hi.w;
            *(float4*)(hp)       = h0;
            *(float4*)(hp + CHI) = h1;
            if (wl_next) {
                float* p = As + (row_base + r) * ASTR + c0;
                *(float4*)(p)       = h0;
                *(float4*)(p + CHI) = h1;
            }
        }
    }
    if (!wl_next) return;
    __syncthreads();

    const float* w1b = wl_next + 4 * WQ_FLOATS;
    acc_init0(acc);
    GEMM_STREAM4F(NTN, Wb0, Wb1, As, wl_next, w1b, row_base, c0, acc);   // P
    store_P_agg(acc, r0, row_base, c0);
    acc_init0(acc);
    GEMM_STREAM4F(NTN, Wb0, Wb1, As, w1b, (const float*)0, row_base, c0, acc);  // Q
    store_Qv(acc, r0, row_base, c0);
}

// ============================ decoder ============================
__global__ __launch_bounds__(NTN, 3)
void dec_kernel(const float* __restrict__ w1, const float* __restrict__ b1,
                const float* __restrict__ aslope,
                const float* __restrict__ w2, const float* __restrict__ b2,
                float* __restrict__ out) {
    extern __shared__ float sm[];
    float* Wb0 = sm;
    float* Wb1 = sm + WQ_FLOATS;
    float* As = sm + 2 * WQ_FLOATS;
    int tid = threadIdx.x;
    int row_base, c0; tmap(tid, row_base, c0);
    int r0 = blockIdx.x * TILEN;

    stage_w<NTN>(Wb0, w1, tid);
    fill_rows<NTN, TILEN>(As, g_h, r0, NN, tid);
    __syncthreads();

    float al = *aslope;
    u64t acc[8][4];
    acc_initb(acc, b1, c0);
    GEMM_STREAM4F(NTN, Wb0, Wb1, As, w1, (const float*)0, row_base, c0, acc);

    __syncthreads();
    store_U(As, acc, row_base, c0, al);
    __syncthreads();

    for (int idx = tid; idx < TILEN * 3; idx += NTN) {
        int r = idx / 3, c = idx - r * 3;
        int gr = r0 + r;
        if (gr < NN) {
            float s = b2[c];
#pragma unroll 8
            for (int k = 0; k < LDIM; ++k)
                s = fmaf(As[r * ASTR + k], w2[k * 3 + c], s);
            out[(size_t)gr * 3 + c] = s;
        }
    }
}

// ============================ host ============================
extern "C" void kernel_launch(void* const* d_in, const int* in_sizes, int n_in,
                              void* d_out, int out_size) {
    const float* x          = (const float*)d_in[0];
    const float* edge_attr  = (const float*)d_in[1];
    const int*   edge_index = (const int*)  d_in[2];
    const float* ne_w1 = (const float*)d_in[3];
    const float* ne_b1 = (const float*)d_in[4];
    const float* ne_a  = (const float*)d_in[5];
    const float* ne_w2 = (const float*)d_in[6];
    const float* ne_b2 = (const float*)d_in[7];
    const float* ee_w1 = (const float*)d_in[8];
    const float* ee_b1 = (const float*)d_in[9];
    const float* ee_a  = (const float*)d_in[10];
    const float* ee_w2 = (const float*)d_in[11];
    const float* ee_b2 = (const float*)d_in[12];
    const float* le_w1 = (const float*)d_in[13];
    const float* le_b1 = (const float*)d_in[14];
    const float* le_a  = (const float*)d_in[15];
    const float* le_w2 = (const float*)d_in[16];
    const float* le_b2 = (const float*)d_in[17];
    const float* ln_w1 = (const float*)d_in[18];
    const float* ln_b1 = (const float*)d_in[19];
    const float* ln_a  = (const float*)d_in[20];
    const float* ln_w2 = (const float*)d_in[21];
    const float* ln_b2 = (const float*)d_in[22];
    const float* de_w1 = (const float*)d_in[23];
    const float* de_b1 = (const float*)d_in[24];
    const float* de_a  = (const float*)d_in[25];
    const float* de_w2 = (const float*)d_in[26];
    const float* de_b2 = (const float*)d_in[27];
    float* out = (float*)d_out;

    float *p_h = nullptr, *p_e = nullptr;
    cudaGetSymbolAddress((void**)&p_h, g_h);
    cudaGetSymbolAddress((void**)&p_e, g_e);

    // one-time stream/event setup (first call is outside graph capture)
    static cudaStream_t s_alt = nullptr;
    static cudaEvent_t ev_fork = nullptr, ev_join = nullptr;
    if (!s_alt) {
        cudaStreamCreateWithFlags(&s_alt, cudaStreamNonBlocking);
        cudaEventCreateWithFlags(&ev_fork, cudaEventDisableTiming);
        cudaEventCreateWithFlags(&ev_join, cudaEventDisableTiming);
    }

    cudaFuncSetAttribute((const void*)encoder_kernel<30,32>, cudaFuncAttributeMaxDynamicSharedMemorySize, SMEM_NODE);
    cudaFuncSetAttribute((const void*)encoder_kernel<4,4>,   cudaFuncAttributeMaxDynamicSharedMemorySize, SMEM_NODE);
    cudaFuncSetAttribute((const void*)edge_kernel, cudaFuncAttributeMaxDynamicSharedMemorySize, SMEM_EDGEK);
    cudaFuncSetAttribute((const void*)node_kernel, cudaFuncAttributeMaxDynamicSharedMemorySize, SMEM_NODE);
    cudaFuncSetAttribute((const void*)dec_kernel,  cudaFuncAttributeMaxDynamicSharedMemorySize, SMEM_NODE);

    const int nb_n = (NN + TILEN - 1) / TILEN;   // 313
    const int nb_e_enc = NE / TILEN;             // 5000
    const int nb_e = NE / TILE;                  // 2500

    // fork: edge encoder on side stream, node encoder (fused layer-0 P/Q) on main
    cudaEventRecord(ev_fork, 0);
    cudaStreamWaitEvent(s_alt, ev_fork, 0);
    encoder_kernel<4,4><<<nb_e_enc, NTN, SMEM_NODE, s_alt>>>(edge_attr, ee_w1, ee_b1, ee_a,
                                                             ee_w2, ee_b2, p_e, NE,
                                                             (const float*)0);
    cudaEventRecord(ev_join, s_alt);

    encoder_kernel<30,32><<<nb_n, NTN, SMEM_NODE>>>(x, ne_w1, ne_b1, ne_a, ne_w2, ne_b2,
                                                    p_h, NN, le_w1);
    cudaStreamWaitEvent(0, ev_join, 0);   // join before layer 0 edge kernel

    for (int l = 0; l < NLAYERS; ++l) {
        const float* wl = le_w1 + (size_t)l * 384 * LDIM;
        edge_kernel<<<nb_e, NT, SMEM_EDGEK>>>(edge_index, wl,
                                              le_b1 + l * LDIM, le_a + l,
                                              le_w2 + (size_t)l * LDIM * LDIM,
                                              le_b2 + l * LDIM);
        const float* wl_next = (l + 1 < NLAYERS) ? (le_w1 + (size_t)(l + 1) * 384 * LDIM)
                                                 : (const float*)0;
        node_kernel<<<nb_n, NTN, SMEM_NODE>>>(ln_w1 + (size_t)l * 256 * LDIM,
                                              ln_b1 + l * LDIM, ln_a + l,
                                              ln_w2 + (size_t)l * LDIM * LDIM,
                                              ln_b2 + l * LDIM,
                                              wl_next);
    }
    dec_kernel<<<nb_n, NTN, SMEM_NODE>>>(de_w1, de_b1, de_a, de_w2, de_b2, out);
}

// round 15
// speedup vs baseline: 1.1162x; 1.1162x over previous
#include <cuda_runtime.h>
#include <stdint.h>

#define NN 20000
#define NE 320000
#define LDIM 128
#define TILE 128              // rows per CTA (edge kernel)
#define TILEN 64              // rows per CTA (node-side kernels)
#define ASTR 132              // padded A/U row stride (floats)
#define NT 256                // threads (edge)
#define NTN 128               // threads (node-side)
#define KQ 32                 // k-quarter staged per cp.async group
#define CHI 64                // column offset of second 4-col chunk per lane
#define NLAYERS 5

#define WQ_FLOATS (KQ * LDIM)                       // 4096 floats = 16KB
#define SMEM_EDGEK ((2 * WQ_FLOATS + TILE * ASTR) * 4 + 2 * TILE * 4)
#define SMEM_NODE  ((2 * WQ_FLOATS + TILEN * ASTR) * 4)

// -------- scratch (static device allocations; no runtime alloc) --------
__device__ float g_h[NN * LDIM];
__device__ float g_P[NN * LDIM];
__device__ float g_Q[NN * LDIM];
__device__ float g_agg[NN * LDIM];
__device__ float g_e[NE * LDIM];

typedef unsigned long long u64t;

// -------- packed fp32x2 primitives --------
__device__ __forceinline__ void ffma2(u64t& d, u64t a, u64t b) {
    asm("fma.rn.f32x2 %0, %1, %2, %0;" : "+l"(d) : "l"(a), "l"(b));
}
__device__ __forceinline__ u64t pack2(float x, float y) {
    u64t v; asm("mov.b64 %0, {%1, %2};" : "=l"(v) : "f"(x), "f"(y)); return v;
}
__device__ __forceinline__ float2 unpack2(u64t v) {
    float2 f; asm("mov.b64 {%0, %1}, %2;" : "=f"(f.x), "=f"(f.y) : "l"(v)); return f;
}
__device__ __forceinline__ float prelu1(float v, float a) { return v > 0.f ? v : a * v; }

__device__ __forceinline__ void red_add_v4(float* addr, float4 v) {
    asm volatile("red.global.add.v4.f32 [%0], {%1,%2,%3,%4};"
                 :: "l"(addr), "f"(v.x), "f"(v.y), "f"(v.z), "f"(v.w)
                 : "memory");
}

// -------- cp.async staging --------
__device__ __forceinline__ uint32_t smem_u32(const void* p) {
    uint32_t a;
    asm("{ .reg .u64 t; cvta.to.shared.u64 t, %1; cvt.u32.u64 %0, t; }" : "=r"(a) : "l"(p));
    return a;
}
__device__ __forceinline__ void cpa16(uint32_t d, const float* __restrict__ s) {
    asm volatile("cp.async.cg.shared.global [%0], [%1], 16;" :: "r"(d), "l"(s));
}
template<int NTT>
__device__ __forceinline__ void stage_w(float* buf, const float* __restrict__ w, int tid) {
    uint32_t d = smem_u32(buf + tid * 4);
    const float* s = w + tid * 4;
#pragma unroll
    for (int i = 0; i < WQ_FLOATS / (NTT * 4); ++i)
        cpa16(d + i * NTT * 16, s + i * NTT * 4);
    asm volatile("cp.async.commit_group;" ::: "memory");
}
#define CPA_WAIT_ALL() asm volatile("cp.async.wait_group 0;" ::: "memory")

// -------- smem fills --------
template<int NTT, int TILER>
__device__ __forceinline__ void fill_rows(float* As, const float* __restrict__ src,
                                          int r0, int nrows, int tid) {
    for (int i = tid * 4; i < TILER * LDIM; i += NTT * 4) {
        int r = i >> 7;
        int k = i & (LDIM - 1);
        int gr = r0 + r; if (gr >= nrows) gr = nrows - 1;
        *(float4*)(As + r * ASTR + k) = *(const float4*)(src + (size_t)gr * LDIM + k);
    }
}

// -------- core packed GEMM (column-paired accumulators, 16 rows/warp) --------
template<int K, int AS>
__device__ __forceinline__ void gemm_cp(const float* __restrict__ As,
                                        const float* __restrict__ Ws,
                                        int row_base, int c0, u64t acc[8][4]) {
#pragma unroll 2
    for (int k = 0; k < K; k += 4) {
        float4 av[8];
#pragma unroll
        for (int r = 0; r < 8; ++r)
            av[r] = *(const float4*)(As + (row_base + r) * AS + k);
#pragma unroll
        for (int kk = 0; kk < 4; ++kk) {
            const float* wr = Ws + (k + kk) * LDIM + c0;
            ulonglong2 w0 = *(const ulonglong2*)(wr);          // cols c0..c0+3
            ulonglong2 w1 = *(const ulonglong2*)(wr + CHI);    // cols c0+64..+67
#pragma unroll
            for (int r = 0; r < 8; ++r) {
                float a = (kk == 0) ? av[r].x : (kk == 1) ? av[r].y
                        : (kk == 2) ? av[r].z : av[r].w;
                u64t ad = pack2(a, a);
                ffma2(acc[r][0], ad, w0.x);
                ffma2(acc[r][1], ad, w0.y);
                ffma2(acc[r][2], ad, w1.x);
                ffma2(acc[r][3], ad, w1.y);
            }
        }
    }
}

__device__ __forceinline__ void acc_initb(u64t acc[8][4], const float* __restrict__ b, int c0) {
    ulonglong2 b0 = *(const ulonglong2*)(b + c0);
    ulonglong2 b1 = *(const ulonglong2*)(b + c0 + CHI);
#pragma unroll
    for (int r = 0; r < 8; ++r) {
        acc[r][0] = b0.x; acc[r][1] = b0.y; acc[r][2] = b1.x; acc[r][3] = b1.y;
    }
}
__device__ __forceinline__ void acc_init0(u64t acc[8][4]) {
#pragma unroll
    for (int r = 0; r < 8; ++r)
        acc[r][0] = acc[r][1] = acc[r][2] = acc[r][3] = 0ull;
}
__device__ __forceinline__ void acc_fin2(const u64t a[4], float4& lo, float4& hi) {
    float2 f0 = unpack2(a[0]), f1 = unpack2(a[1]), f2 = unpack2(a[2]), f3 = unpack2(a[3]);
    lo = make_float4(f0.x, f0.y, f1.x, f1.y);
    hi = make_float4(f2.x, f2.y, f3.x, f3.y);
}
__device__ __forceinline__ void store_U(float* U, u64t acc[8][4],
                                        int row_base, int c0, float al) {
#pragma unroll
    for (int r = 0; r < 8; ++r) {
        float4 lo, hi; acc_fin2(acc[r], lo, hi);
        lo.x = prelu1(lo.x, al); lo.y = prelu1(lo.y, al);
        lo.z = prelu1(lo.z, al); lo.w = prelu1(lo.w, al);
        hi.x = prelu1(hi.x, al); hi.y = prelu1(hi.y, al);
        hi.z = prelu1(hi.z, al); hi.w = prelu1(hi.w, al);
        float* p = U + (row_base + r) * ASTR + c0;
        *(float4*)(p)       = lo;
        *(float4*)(p + CHI) = hi;
    }
}
__device__ __forceinline__ void tmap(int tid, int& row_base, int& c0) {
    int wy = tid >> 5;
    int lane = tid & 31;
    row_base = wy * 16 + (lane >> 4) * 8;
    c0 = (lane & 15) * 4;
}

// Run 4 streamed quarters of one 128-K GEMM. q0 must already be staged into WbA.
#define GEMM_STREAM4(NTT, WbA, WbB, As, wsrc, nxt, row_base, c0, acc)                    \
    do {                                                                                 \
        _Pragma("unroll")                                                                \
        for (int q = 0; q < 4; ++q) {                                                    \
            CPA_WAIT_ALL(); __syncthreads();                                             \
            const float* _n = (q < 3) ? ((wsrc) + (q + 1) * WQ_FLOATS) : (nxt);          \
            if (_n) stage_w<NTT>((q & 1) ? (WbA) : (WbB), _n, tid);                      \
            gemm_cp<KQ, ASTR>((As) + q * KQ, (q & 1) ? (WbB) : (WbA), row_base, c0, acc);\
        }                                                                                \
    } while (0)

// write P/agg-zero epilogue
__device__ __forceinline__ void store_P_agg(u64t acc[8][4], int r0, int row_base, int c0) {
    float4 z = make_float4(0.f, 0.f, 0.f, 0.f);
#pragma unroll
    for (int r = 0; r < 8; ++r) {
        int gr = r0 + row_base + r;
        if (gr < NN) {
            float4 lo, hi; acc_fin2(acc[r], lo, hi);
            *(float4*)(g_P + (size_t)gr * LDIM + c0)         = lo;
            *(float4*)(g_P + (size_t)gr * LDIM + c0 + CHI)   = hi;
            *(float4*)(g_agg + (size_t)gr * LDIM + c0)       = z;
            *(float4*)(g_agg + (size_t)gr * LDIM + c0 + CHI) = z;
        }
    }
}
__device__ __forceinline__ void store_Qv(u64t acc[8][4], int r0, int row_base, int c0) {
#pragma unroll
    for (int r = 0; r < 8; ++r) {
        int gr = r0 + row_base + r;
        if (gr < NN) {
            float4 lo, hi; acc_fin2(acc[r], lo, hi);
            *(float4*)(g_Q + (size_t)gr * LDIM + c0)       = lo;
            *(float4*)(g_Q + (size_t)gr * LDIM + c0 + CHI) = hi;
        }
    }
}

// ============================ encoder (node fused with layer-0 P/Q; edge plain) ====
template<int K1, int K1P>
__global__ __launch_bounds__(NTN, 3)
void encoder_kernel(const float* __restrict__ in,
                    const float* __restrict__ w1, const float* __restrict__ b1,
                    const float* __restrict__ aslope,
                    const float* __restrict__ w2, const float* __restrict__ b2,
                    float* __restrict__ out, int nrows,
                    const float* __restrict__ wl /* le_w1 layer0 base or null */) {
    extern __shared__ float sm[];
    float* Wb0 = sm;
    float* Wb1 = sm + WQ_FLOATS;
    float* As = sm + 2 * WQ_FLOATS;
    int tid = threadIdx.x;
    int row_base, c0; tmap(tid, row_base, c0);
    int r0 = blockIdx.x * TILEN;

    for (int i = tid; i < TILEN * K1P; i += NTN) {
        int r = i / K1P, k = i - r * K1P;
        int gr = r0 + r; if (gr >= nrows) gr = nrows - 1;
        As[i] = (k < K1) ? in[(size_t)gr * K1 + k] : 0.f;
    }
    for (int i = tid; i < K1P * LDIM; i += NTN)
        Wb0[i] = (i < K1 * LDIM) ? w1[i] : 0.f;
    __syncthreads();

    stage_w<NTN>(Wb1, w2, tid);            // prefetch W2 q0 during GEMM1 (q0 -> Wb1)
    float al = *aslope;

    u64t acc[8][4];
    acc_initb(acc, b1, c0);
    gemm_cp<K1P, K1P>(As, Wb0, row_base, c0, acc);

    __syncthreads();
    store_U(As, acc, row_base, c0, al);
    acc_initb(acc, b2, c0);

    GEMM_STREAM4(NTN, Wb1, Wb0, As, w2, wl, row_base, c0, acc);  // h; prefetch W1a q0

    __syncthreads();
#pragma unroll
    for (int r = 0; r < 8; ++r) {
        int gr = r0 + row_base + r;
        float4 lo, hi; acc_fin2(acc[r], lo, hi);
        if (gr < nrows) {
            *(float4*)(out + (size_t)gr * LDIM + c0)       = lo;
            *(float4*)(out + (size_t)gr * LDIM + c0 + CHI) = hi;
        }
        if (wl) {
            float* p = As + (row_base + r) * ASTR + c0;
            *(float4*)(p)       = lo;
            *(float4*)(p + CHI) = hi;
        }
    }
    if (!wl) return;
    __syncthreads();

    const float* w1b = wl + 4 * WQ_FLOATS;
    acc_init0(acc);
    GEMM_STREAM4(NTN, Wb1, Wb0, As, wl, w1b, row_base, c0, acc);   // P
    store_P_agg(acc, r0, row_base, c0);
    acc_init0(acc);
    GEMM_STREAM4(NTN, Wb1, Wb0, As, w1b, (const float*)0, row_base, c0, acc);  // Q
    store_Qv(acc, r0, row_base, c0);
}

// ============================ per-layer: edge messages + scatter ============================
__global__ __launch_bounds__(NT, 2)
void edge_kernel(const int* __restrict__ eidx,
                 const float* __restrict__ wl,
                 const float* __restrict__ b1, const float* __restrict__ aslope,
                 const float* __restrict__ w2, const float* __restrict__ b2) {
    extern __shared__ float sm[];
    float* Wb0 = sm;
    float* Wb1 = sm + WQ_FLOATS;
    float* As = sm + 2 * WQ_FLOATS;
    int* sdst = (int*)(As + TILE * ASTR);
    int* ssrc = sdst + TILE;
    int tid = threadIdx.x;
    int row_base, c0; tmap(tid, row_base, c0);
    size_t e0 = (size_t)blockIdx.x * TILE;

    const float* w1c = wl + 256 * LDIM;
    stage_w<NT>(Wb0, w1c, tid);                      // W1c q0
    fill_rows<NT, TILE>(As, g_e + e0 * LDIM, 0, TILE, tid);
    if (tid < TILE) {
        ssrc[tid] = eidx[e0 + tid];
        sdst[tid] = eidx[NE + e0 + tid];
    }
    __syncthreads();

    float al = *aslope;
    float4 ba = *(const float4*)(b1 + c0);
    float4 bb = *(const float4*)(b1 + c0 + CHI);
    u64t acc[8][4];
#pragma unroll
    for (int r = 0; r < 8; ++r) {
        int d = sdst[row_base + r];
        int s = ssrc[row_base + r];
        float4 Pa = *(const float4*)(g_P + (size_t)d * LDIM + c0);
        float4 Pb = *(const float4*)(g_P + (size_t)d * LDIM + c0 + CHI);
        float4 Qa = *(const float4*)(g_Q + (size_t)s * LDIM + c0);
        float4 Qb = *(const float4*)(g_Q + (size_t)s * LDIM + c0 + CHI);
        acc[r][0] = pack2(ba.x + Pa.x + Qa.x, ba.y + Pa.y + Qa.y);
        acc[r][1] = pack2(ba.z + Pa.z + Qa.z, ba.w + Pa.w + Qa.w);
        acc[r][2] = pack2(bb.x + Pb.x + Qb.x, bb.y + Pb.y + Qb.y);
        acc[r][3] = pack2(bb.z + Pb.z + Qb.z, bb.w + Pb.w + Qb.w);
    }
    GEMM_STREAM4(NT, Wb0, Wb1, As, w1c, w2, row_base, c0, acc);   // W1c, prefetch W2 q0

    __syncthreads();
    store_U(As, acc, row_base, c0, al);
    acc_initb(acc, b2, c0);
    GEMM_STREAM4(NT, Wb0, Wb1, As, w2, (const float*)0, row_base, c0, acc);  // W2

#pragma unroll
    for (int r = 0; r < 8; ++r) {
        int d = sdst[row_base + r];
        float4 lo, hi; acc_fin2(acc[r], lo, hi);
        red_add_v4(g_agg + (size_t)d * LDIM + c0, lo);
        red_add_v4(g_agg + (size_t)d * LDIM + c0 + CHI, hi);
    }
}

// ============================ per-layer: node update (fused with next-layer P/Q) ====
__global__ __launch_bounds__(NTN, 3)
void node_kernel(const float* __restrict__ wn1,
                 const float* __restrict__ b1, const float* __restrict__ aslope,
                 const float* __restrict__ w2, const float* __restrict__ b2,
                 const float* __restrict__ wl_next /* le_w1 next layer or null */) {
    extern __shared__ float sm[];
    float* Wb0 = sm;
    float* Wb1 = sm + WQ_FLOATS;
    float* As = sm + 2 * WQ_FLOATS;
    int tid = threadIdx.x;
    int row_base, c0; tmap(tid, row_base, c0);
    int r0 = blockIdx.x * TILEN;

    const float* wagg = wn1 + 4 * WQ_FLOATS;
    stage_w<NTN>(Wb0, wn1, tid);
    fill_rows<NTN, TILEN>(As, g_h, r0, NN, tid);
    __syncthreads();

    float al = *aslope;
    u64t acc[8][4];
    acc_initb(acc, b1, c0);
    GEMM_STREAM4(NTN, Wb0, Wb1, As, wn1, wagg, row_base, c0, acc);   // h side

    __syncthreads();
    fill_rows<NTN, TILEN>(As, g_agg, r0, NN, tid);
    GEMM_STREAM4(NTN, Wb0, Wb1, As, wagg, w2, row_base, c0, acc);    // agg side

    __syncthreads();
    store_U(As, acc, row_base, c0, al);
    acc_initb(acc, b2, c0);
    GEMM_STREAM4(NTN, Wb0, Wb1, As, w2, wl_next, row_base, c0, acc); // W2; prefetch W1a

    __syncthreads();
#pragma unroll
    for (int r = 0; r < 8; ++r) {
        int gr = r0 + row_base + r;
        if (gr < NN) {
            float4 lo, hi; acc_fin2(acc[r], lo, hi);
            float* hp = g_h + (size_t)gr * LDIM + c0;
            float4 h0 = *(float4*)(hp);
            float4 h1 = *(float4*)(hp + CHI);
            h0.x += lo.x; h0.y += lo.y; h0.z += lo.z; h0.w += lo.w;
            h1.x += hi.x; h1.y += hi.y; h1.z += hi.z; h1.w += hi.w;
            *(float4*)(hp)       = h0;
            *(float4*)(hp + CHI) = h1;
            if (wl_next) {
                float* p = As + (row_base + r) * ASTR + c0;
                *(float4*)(p)       = h0;
                *(float4*)(p + CHI) = h1;
            }
        }
    }
    if (!wl_next) return;
    __syncthreads();

    const float* w1b = wl_next + 4 * WQ_FLOATS;
    acc_init0(acc);
    GEMM_STREAM4(NTN, Wb0, Wb1, As, wl_next, w1b, row_base, c0, acc);   // P
    store_P_agg(acc, r0, row_base, c0);
    acc_init0(acc);
    GEMM_STREAM4(NTN, Wb0, Wb1, As, w1b, (const float*)0, row_base, c0, acc);  // Q
    store_Qv(acc, r0, row_base, c0);
}

// ============================ decoder ============================
__global__ __launch_bounds__(NTN, 3)
void dec_kernel(const float* __restrict__ w1, const float* __restrict__ b1,
                const float* __restrict__ aslope,
                const float* __restrict__ w2, const float* __restrict__ b2,
                float* __restrict__ out) {
    extern __shared__ float sm[];
    float* Wb0 = sm;
    float* Wb1 = sm + WQ_FLOATS;
    float* As = sm + 2 * WQ_FLOATS;
    int tid = threadIdx.x;
    int row_base, c0; tmap(tid, row_base, c0);
    int r0 = blockIdx.x * TILEN;

    stage_w<NTN>(Wb0, w1, tid);
    fill_rows<NTN, TILEN>(As, g_h, r0, NN, tid);
    __syncthreads();

    float al = *aslope;
    u64t acc[8][4];
    acc_initb(acc, b1, c0);
    GEMM_STREAM4(NTN, Wb0, Wb1, As, w1, (const float*)0, row_base, c0, acc);

    __syncthreads();
    store_U(As, acc, row_base, c0, al);
    __syncthreads();

    for (int idx = tid; idx < TILEN * 3; idx += NTN) {
        int r = idx / 3, c = idx - r * 3;
        int gr = r0 + r;
        if (gr < NN) {
            float s = b2[c];
#pragma unroll 8
            for (int k = 0; k < LDIM; ++k)
                s = fmaf(As[r * ASTR + k], w2[k * 3 + c], s);
            out[(size_t)gr * 3 + c] = s;
        }
    }
}

// ============================ host ============================
extern "C" void kernel_launch(void* const* d_in, const int* in_sizes, int n_in,
                              void* d_out, int out_size) {
    const float* x          = (const float*)d_in[0];
    const float* edge_attr  = (const float*)d_in[1];
    const int*   edge_index = (const int*)  d_in[2];
    const float* ne_w1 = (const float*)d_in[3];
    const float* ne_b1 = (const float*)d_in[4];
    const float* ne_a  = (const float*)d_in[5];
    const float* ne_w2 = (const float*)d_in[6];
    const float* ne_b2 = (const float*)d_in[7];
    const float* ee_w1 = (const float*)d_in[8];
    const float* ee_b1 = (const float*)d_in[9];
    const float* ee_a  = (const float*)d_in[10];
    const float* ee_w2 = (const float*)d_in[11];
    const float* ee_b2 = (const float*)d_in[12];
    const float* le_w1 = (const float*)d_in[13];
    const float* le_b1 = (const float*)d_in[14];
    const float* le_a  = (const float*)d_in[15];
    const float* le_w2 = (const float*)d_in[16];
    const float* le_b2 = (const float*)d_in[17];
    const float* ln_w1 = (const float*)d_in[18];
    const float* ln_b1 = (const float*)d_in[19];
    const float* ln_a  = (const float*)d_in[20];
    const float* ln_w2 = (const float*)d_in[21];
    const float* ln_b2 = (const float*)d_in[22];
    const float* de_w1 = (const float*)d_in[23];
    const float* de_b1 = (const float*)d_in[24];
    const float* de_a  = (const float*)d_in[25];
    const float* de_w2 = (const float*)d_in[26];
    const float* de_b2 = (const float*)d_in[27];
    float* out = (float*)d_out;

    float *p_h = nullptr, *p_e = nullptr;
    cudaGetSymbolAddress((void**)&p_h, g_h);
    cudaGetSymbolAddress((void**)&p_e, g_e);

    // one-time stream/event setup (first call is outside graph capture)
    static cudaStream_t s_alt = nullptr;
    static cudaEvent_t ev_fork = nullptr, ev_join = nullptr;
    if (!s_alt) {
        cudaStreamCreateWithFlags(&s_alt, cudaStreamNonBlocking);
        cudaEventCreateWithFlags(&ev_fork, cudaEventDisableTiming);
        cudaEventCreateWithFlags(&ev_join, cudaEventDisableTiming);
    }

    cudaFuncSetAttribute((const void*)encoder_kernel<30,32>, cudaFuncAttributeMaxDynamicSharedMemorySize, SMEM_NODE);
    cudaFuncSetAttribute((const void*)encoder_kernel<4,4>,   cudaFuncAttributeMaxDynamicSharedMemorySize, SMEM_NODE);
    cudaFuncSetAttribute((const void*)edge_kernel, cudaFuncAttributeMaxDynamicSharedMemorySize, SMEM_EDGEK);
    cudaFuncSetAttribute((const void*)node_kernel, cudaFuncAttributeMaxDynamicSharedMemorySize, SMEM_NODE);
    cudaFuncSetAttribute((const void*)dec_kernel,  cudaFuncAttributeMaxDynamicSharedMemorySize, SMEM_NODE);

    const int nb_n = (NN + TILEN - 1) / TILEN;   // 313
    const int nb_e_enc = NE / TILEN;             // 5000
    const int nb_e = NE / TILE;                  // 2500

    // fork: edge encoder on side stream, node encoder (fused layer-0 P/Q) on main
    cudaEventRecord(ev_fork, 0);
    cudaStreamWaitEvent(s_alt, ev_fork, 0);
    encoder_kernel<4,4><<<nb_e_enc, NTN, SMEM_NODE, s_alt>>>(edge_attr, ee_w1, ee_b1, ee_a,
                                                             ee_w2, ee_b2, p_e, NE,
                                                             (const float*)0);
    cudaEventRecord(ev_join, s_alt);

    encoder_kernel<30,32><<<nb_n, NTN, SMEM_NODE>>>(x, ne_w1, ne_b1, ne_a, ne_w2, ne_b2,
                                                    p_h, NN, le_w1);
    cudaStreamWaitEvent(0, ev_join, 0);   // join before layer 0 edge kernel

    for (int l = 0; l < NLAYERS; ++l) {
        const float* wl = le_w1 + (size_t)l * 384 * LDIM;
        edge_kernel<<<nb_e, NT, SMEM_EDGEK>>>(edge_index, wl,
                                              le_b1 + l * LDIM, le_a + l,
                                              le_w2 + (size_t)l * LDIM * LDIM,
                                              le_b2 + l * LDIM);
        const float* wl_next = (l + 1 < NLAYERS) ? (le_w1 + (size_t)(l + 1) * 384 * LDIM)
                                                 : (const float*)0;
        node_kernel<<<nb_n, NTN, SMEM_NODE>>>(ln_w1 + (size_t)l * 256 * LDIM,
                                              ln_b1 + l * LDIM, ln_a + l,
                                              ln_w2 + (size_t)l * LDIM * LDIM,
                                              ln_b2 + l * LDIM,
                                              wl_next);
    }
    dec_kernel<<<nb_n, NTN, SMEM_NODE>>>(de_w1, de_b1, de_a, de_w2, de_b2, out);
}